// round 15
// baseline (speedup 1.0000x reference)
#include <cuda_runtime.h>

#define BATCH 8
#define NROWS 10000
#define CDIM 256
#define CTAS_PER_BATCH 74
#define GRID (BATCH * CTAS_PER_BATCH)   // 592 = 4 CTAs * 148 SMs, single wave
#define THREADS 256
#define CACHE_ROWS 48                   // rows cached in SMEM per CTA (48 KB)
#define LN_EPS 1e-5f

// Shared memory layout (floats):
#define SM_CACHE 0                       // 12288 floats: cached x rows
#define SM_RED   12288                   // 1024 floats: float4 staging / smean
#define SM_AGG   13312                   // 256
#define SM_GAM   13568                   // 256
#define SM_BET   13824                   // 256
#define SM_FLOATS 14080                  // 56320 bytes total

// Scratch (allocation-free rule: __device__ globals)
__device__ float g_partial[GRID][CDIM];
__device__ float g_agg[BATCH][CDIM];
__device__ unsigned int g_bar1 = 0;
__device__ unsigned int g_bar2 = 0;

// Grid-wide barrier, safe across graph replays (no counter reset needed):
// each launch adds exactly GRID; target is the next multiple of GRID above v.
__device__ __forceinline__ void grid_barrier(unsigned int* bar) {
    __threadfence();
    __syncthreads();
    if (threadIdx.x == 0) {
        unsigned int v = atomicAdd(bar, 1u);
        unsigned int target = v - (v % GRID) + GRID;
        while (*(volatile unsigned int*)bar < target) __nanosleep(64);
        __threadfence();
    }
    __syncthreads();
}

__global__ void __launch_bounds__(THREADS, 4)
fused_gcn_ln_kernel(const float* __restrict__ x,
                    const float* __restrict__ W,
                    const float* __restrict__ bias,
                    const float* __restrict__ gamma,
                    const float* __restrict__ beta,
                    float* __restrict__ out) {
    extern __shared__ float smem[];
    const int t = threadIdx.x;
    const int warp = t >> 5;
    const int lane = t & 31;

    const int bb = blockIdx.x / CTAS_PER_BATCH;   // batch
    const int k  = blockIdx.x % CTAS_PER_BATCH;   // cta within batch
    // 10000 = 74*135 + 10 -> first 10 CTAs take 136 rows
    const int count = (k < 10) ? 136 : 135;
    const int base_in_batch = k * 135 + ((k < 10) ? k : 10);
    const long gbase = (long)bb * NROWS + base_in_batch;

    float4* cache4 = (float4*)(smem + SM_CACHE);

    // ---------------- Phase 1: column sums + SMEM cache fill ----------------
    {
        const int qc = t & 63;    // float4 column
        const int rg = t >> 6;    // row group 0..3
        const float4* xb = (const float4*)(x + gbase * CDIM) + qc;

        float4 a0 = make_float4(0.f, 0.f, 0.f, 0.f);
        float4 a1 = make_float4(0.f, 0.f, 0.f, 0.f);
        int r = rg;
        for (; r + 4 < count; r += 8) {
            float4 v0 = xb[(size_t)r * 64];
            float4 v1 = xb[(size_t)(r + 4) * 64];
            if (r < CACHE_ROWS)     cache4[r * 64 + qc] = v0;
            if (r + 4 < CACHE_ROWS) cache4[(r + 4) * 64 + qc] = v1;
            a0.x += v0.x; a0.y += v0.y; a0.z += v0.z; a0.w += v0.w;
            a1.x += v1.x; a1.y += v1.y; a1.z += v1.z; a1.w += v1.w;
        }
        if (r < count) {
            float4 v0 = xb[(size_t)r * 64];
            if (r < CACHE_ROWS) cache4[r * 64 + qc] = v0;
            a0.x += v0.x; a0.y += v0.y; a0.z += v0.z; a0.w += v0.w;
        }
        a0.x += a1.x; a0.y += a1.y; a0.z += a1.z; a0.w += a1.w;

        float4* red = (float4*)(smem + SM_RED);
        red[t] = a0;
        __syncthreads();
        if (t < 64) {
            float4 a = red[t];
            float4 c1 = red[t + 64];
            float4 c2 = red[t + 128];
            float4 c3 = red[t + 192];
            a.x += c1.x + c2.x + c3.x;
            a.y += c1.y + c2.y + c3.y;
            a.z += c1.z + c2.z + c3.z;
            a.w += c1.w + c2.w + c3.w;
            ((float4*)&g_partial[blockIdx.x][0])[t] = a;
        }
    }

    grid_barrier(&g_bar1);

    // ---------------- Leader CTAs: finish mean + tiny GEMM ----------------
    if (k == 0) {
        float* smean = smem + SM_RED;   // reuse staging
        float s = 0.0f;
#pragma unroll
        for (int j = 0; j < CTAS_PER_BATCH; ++j)
            s += g_partial[bb * CTAS_PER_BATCH + j][t];
        smean[t] = s * (1.0f / (float)NROWS);
        __syncthreads();

        for (int c = warp; c < CDIM; c += 8) {
            const float* wr = W + (size_t)c * CDIM;
            float d = 0.0f;
#pragma unroll
            for (int kk = lane; kk < CDIM; kk += 32)
                d += wr[kk] * smean[kk];
#pragma unroll
            for (int off = 16; off > 0; off >>= 1)
                d += __shfl_down_sync(0xffffffffu, d, off);
            if (lane == 0) g_agg[bb][c] = d + bias[c];
        }
    }

    grid_barrier(&g_bar2);

    // ---------------- Phase 2: residual + LayerNorm ----------------
    float* sh_agg = smem + SM_AGG;
    float* sh_g = smem + SM_GAM;
    float* sh_b = smem + SM_BET;
    sh_agg[t] = g_agg[bb][t];
    sh_g[t] = gamma[t];
    sh_b[t] = beta[t];
    __syncthreads();

    const int li = lane * 2;
    const float4 ag0 = ((const float4*)sh_agg)[li];
    const float4 ag1 = ((const float4*)sh_agg)[li + 1];
    const float4 g0 = ((const float4*)sh_g)[li];
    const float4 g1 = ((const float4*)sh_g)[li + 1];
    const float4 b0 = ((const float4*)sh_b)[li];
    const float4 b1 = ((const float4*)sh_b)[li + 1];
    const float inv = 1.0f / (float)CDIM;

    // Warp w handles row pairs {2w, 2w+1} + multiples of 16
    for (int r0 = warp * 2; r0 < count; r0 += 16) {
        const int r1 = r0 + 1;
        const bool two = (r1 < count);

        float4 p0, p1, q0, q1;
        if (r0 < CACHE_ROWS) {
            p0 = cache4[r0 * 64 + li];
            p1 = cache4[r0 * 64 + li + 1];
        } else {
            const float4* xr = (const float4*)(x + (gbase + r0) * (long)CDIM);
            p0 = xr[li]; p1 = xr[li + 1];
        }
        if (two) {
            if (r1 < CACHE_ROWS) {
                q0 = cache4[r1 * 64 + li];
                q1 = cache4[r1 * 64 + li + 1];
            } else {
                const float4* xr = (const float4*)(x + (gbase + r1) * (long)CDIM);
                q0 = xr[li]; q1 = xr[li + 1];
            }
        } else {
            q0 = make_float4(0.f, 0.f, 0.f, 0.f);
            q1 = make_float4(0.f, 0.f, 0.f, 0.f);
        }

        float ya[8], yb[8];
        ya[0] = p0.x + ag0.x; ya[1] = p0.y + ag0.y;
        ya[2] = p0.z + ag0.z; ya[3] = p0.w + ag0.w;
        ya[4] = p1.x + ag1.x; ya[5] = p1.y + ag1.y;
        ya[6] = p1.z + ag1.z; ya[7] = p1.w + ag1.w;
        yb[0] = q0.x + ag0.x; yb[1] = q0.y + ag0.y;
        yb[2] = q0.z + ag0.z; yb[3] = q0.w + ag0.w;
        yb[4] = q1.x + ag1.x; yb[5] = q1.y + ag1.y;
        yb[6] = q1.z + ag1.z; yb[7] = q1.w + ag1.w;

        float s0 = 0.f, ss0 = 0.f, s1 = 0.f, ss1 = 0.f;
#pragma unroll
        for (int i = 0; i < 8; ++i) {
            s0 += ya[i]; ss0 += ya[i] * ya[i];
            s1 += yb[i]; ss1 += yb[i] * yb[i];
        }
#pragma unroll
        for (int off = 16; off > 0; off >>= 1) {
            s0  += __shfl_xor_sync(0xffffffffu, s0, off);
            ss0 += __shfl_xor_sync(0xffffffffu, ss0, off);
            s1  += __shfl_xor_sync(0xffffffffu, s1, off);
            ss1 += __shfl_xor_sync(0xffffffffu, ss1, off);
        }

        const float mu0 = s0 * inv;
        const float mu1 = s1 * inv;
        const float rs0 = rsqrtf(ss0 * inv - mu0 * mu0 + LN_EPS);
        const float rs1 = rsqrtf(ss1 * inv - mu1 * mu1 + LN_EPS);

        float4 o;
        float4* or0 = (float4*)(out + (gbase + r0) * (long)CDIM);
        o.x = (ya[0] - mu0) * rs0 * g0.x + b0.x;
        o.y = (ya[1] - mu0) * rs0 * g0.y + b0.y;
        o.z = (ya[2] - mu0) * rs0 * g0.z + b0.z;
        o.w = (ya[3] - mu0) * rs0 * g0.w + b0.w;
        or0[li] = o;
        o.x = (ya[4] - mu0) * rs0 * g1.x + b1.x;
        o.y = (ya[5] - mu0) * rs0 * g1.y + b1.y;
        o.z = (ya[6] - mu0) * rs0 * g1.z + b1.z;
        o.w = (ya[7] - mu0) * rs0 * g1.w + b1.w;
        or0[li + 1] = o;
        if (two) {
            float4* or1 = (float4*)(out + (gbase + r1) * (long)CDIM);
            o.x = (yb[0] - mu1) * rs1 * g0.x + b0.x;
            o.y = (yb[1] - mu1) * rs1 * g0.y + b0.y;
            o.z = (yb[2] - mu1) * rs1 * g0.z + b0.z;
            o.w = (yb[3] - mu1) * rs1 * g0.w + b0.w;
            or1[li] = o;
            o.x = (yb[4] - mu1) * rs1 * g1.x + b1.x;
            o.y = (yb[5] - mu1) * rs1 * g1.y + b1.y;
            o.z = (yb[6] - mu1) * rs1 * g1.z + b1.z;
            o.w = (yb[7] - mu1) * rs1 * g1.w + b1.w;
            or1[li + 1] = o;
        }
    }
}

extern "C" void kernel_launch(void* const* d_in, const int* in_sizes, int n_in,
                              void* d_out, int out_size) {
    const float* x     = (const float*)d_in[0];
    const float* W     = (const float*)d_in[1];
    const float* bias  = (const float*)d_in[2];
    const float* gamma = (const float*)d_in[3];
    const float* beta  = (const float*)d_in[4];
    float* out = (float*)d_out;

    const int smem_bytes = SM_FLOATS * (int)sizeof(float);   // 56320
    cudaFuncSetAttribute(fused_gcn_ln_kernel,
                         cudaFuncAttributeMaxDynamicSharedMemorySize, smem_bytes);
    fused_gcn_ln_kernel<<<GRID, THREADS, smem_bytes>>>(x, W, bias, gamma, beta, out);
}

// round 16
// speedup vs baseline: 1.0018x; 1.0018x over previous
#include <cuda_runtime.h>

#define BATCH 8
#define NROWS 10000
#define CDIM 256
#define CTAS_PER_BATCH 74
#define GRID (BATCH * CTAS_PER_BATCH)   // 592 = 4 CTAs * 148 SMs, single wave
#define THREADS 256
#define CACHE_ROWS 48                   // rows cached in SMEM per CTA (48 KB)
#define LN_EPS 1e-5f

// Shared memory layout (floats):
#define SM_CACHE 0                       // 12288 floats: cached x rows
#define SM_RED   12288                   // 1024 floats: float4 staging / smean
#define SM_AGG   13312                   // 256
#define SM_GAM   13568                   // 256
#define SM_BET   13824                   // 256
#define SM_FLOATS 14080                  // 56320 bytes total

// Scratch (allocation-free rule: __device__ globals)
__device__ float g_partial[GRID][CDIM];
__device__ float g_agg[BATCH][CDIM];
__device__ unsigned int g_cnt[BATCH];    // per-batch arrival counters (never reset)
__device__ unsigned int g_flag[BATCH];   // per-batch completion epochs (never reset)

__global__ void __launch_bounds__(THREADS, 4)
fused_gcn_ln_kernel(const float* __restrict__ x,
                    const float* __restrict__ W,
                    const float* __restrict__ bias,
                    const float* __restrict__ gamma,
                    const float* __restrict__ beta,
                    float* __restrict__ out) {
    extern __shared__ float smem[];
    const int t = threadIdx.x;
    const int warp = t >> 5;
    const int lane = t & 31;

    const int bb = blockIdx.x / CTAS_PER_BATCH;   // batch
    const int k  = blockIdx.x % CTAS_PER_BATCH;   // cta within batch
    // 10000 = 74*135 + 10 -> first 10 CTAs take 136 rows
    const int count = (k < 10) ? 136 : 135;
    const int base_in_batch = k * 135 + ((k < 10) ? k : 10);
    const long gbase = (long)bb * NROWS + base_in_batch;

    float4* cache4 = (float4*)(smem + SM_CACHE);

    // ---------------- Phase 1: column sums + SMEM cache fill ----------------
    {
        const int qc = t & 63;    // float4 column
        const int rg = t >> 6;    // row group 0..3
        const float4* xb = (const float4*)(x + gbase * CDIM) + qc;

        float4 a0 = make_float4(0.f, 0.f, 0.f, 0.f);
        float4 a1 = make_float4(0.f, 0.f, 0.f, 0.f);
        int r = rg;
        for (; r + 4 < count; r += 8) {
            float4 v0 = xb[(size_t)r * 64];
            float4 v1 = xb[(size_t)(r + 4) * 64];
            if (r < CACHE_ROWS)     cache4[r * 64 + qc] = v0;
            if (r + 4 < CACHE_ROWS) cache4[(r + 4) * 64 + qc] = v1;
            a0.x += v0.x; a0.y += v0.y; a0.z += v0.z; a0.w += v0.w;
            a1.x += v1.x; a1.y += v1.y; a1.z += v1.z; a1.w += v1.w;
        }
        if (r < count) {
            float4 v0 = xb[(size_t)r * 64];
            if (r < CACHE_ROWS) cache4[r * 64 + qc] = v0;
            a0.x += v0.x; a0.y += v0.y; a0.z += v0.z; a0.w += v0.w;
        }
        a0.x += a1.x; a0.y += a1.y; a0.z += a1.z; a0.w += a1.w;

        float4* red = (float4*)(smem + SM_RED);
        red[t] = a0;
        __syncthreads();
        if (t < 64) {
            float4 a = red[t];
            float4 c1 = red[t + 64];
            float4 c2 = red[t + 128];
            float4 c3 = red[t + 192];
            a.x += c1.x + c2.x + c3.x;
            a.y += c1.y + c2.y + c3.y;
            a.z += c1.z + c2.z + c3.z;
            a.w += c1.w + c2.w + c3.w;
            ((float4*)&g_partial[blockIdx.x][0])[t] = a;
        }
    }

    // ---------------- Per-batch sync: last arriver computes the GEMM --------
    // Replay-safe epochs: counters/flags only ever increment; each launch adds
    // exactly CTAS_PER_BATCH arrivals and 1 flag bump per batch.
    __shared__ unsigned int s_v;
    __syncthreads();                      // g_partial stores done (block scope)
    if (t == 0) {
        __threadfence();                  // publish g_partial
        s_v = atomicAdd(&g_cnt[bb], 1u);
    }
    __syncthreads();
    const unsigned int v = s_v;
    const unsigned int epoch = v / CTAS_PER_BATCH;
    const bool is_last = (v % CTAS_PER_BATCH) == (CTAS_PER_BATCH - 1);

    if (is_last) {
        // All 74 partials for this batch are published; compute mean + GEMM.
        if (t == 0) __threadfence();      // acquire for g_partial reads
        __syncthreads();
        float* smean = smem + SM_RED;
        float s = 0.0f;
#pragma unroll
        for (int j = 0; j < CTAS_PER_BATCH; ++j)
            s += g_partial[bb * CTAS_PER_BATCH + j][t];
        smean[t] = s * (1.0f / (float)NROWS);
        __syncthreads();

        for (int c = warp; c < CDIM; c += 8) {
            const float* wr = W + (size_t)c * CDIM;
            float d = 0.0f;
#pragma unroll
            for (int kk = lane; kk < CDIM; kk += 32)
                d += wr[kk] * smean[kk];
#pragma unroll
            for (int off = 16; off > 0; off >>= 1)
                d += __shfl_down_sync(0xffffffffu, d, off);
            if (lane == 0) g_agg[bb][c] = d + bias[c];
        }
        __syncthreads();
        if (t == 0) {
            __threadfence();              // publish g_agg
            atomicAdd(&g_flag[bb], 1u);
        }
        __syncthreads();
    } else {
        if (t == 0) {
            while (*(volatile unsigned int*)&g_flag[bb] < epoch + 1u)
                __nanosleep(64);
            __threadfence();              // acquire for g_agg reads
        }
        __syncthreads();
    }

    // ---------------- Phase 2: residual + LayerNorm ----------------
    float* sh_agg = smem + SM_AGG;
    float* sh_g = smem + SM_GAM;
    float* sh_b = smem + SM_BET;
    sh_agg[t] = g_agg[bb][t];
    sh_g[t] = gamma[t];
    sh_b[t] = beta[t];
    __syncthreads();

    const int li = lane * 2;
    const float4 ag0 = ((const float4*)sh_agg)[li];
    const float4 ag1 = ((const float4*)sh_agg)[li + 1];
    const float4 g0 = ((const float4*)sh_g)[li];
    const float4 g1 = ((const float4*)sh_g)[li + 1];
    const float4 b0 = ((const float4*)sh_b)[li];
    const float4 b1 = ((const float4*)sh_b)[li + 1];
    const float inv = 1.0f / (float)CDIM;

    // Warp w handles row pairs {2w, 2w+1} + multiples of 16
    for (int r0 = warp * 2; r0 < count; r0 += 16) {
        const int r1 = r0 + 1;
        const bool two = (r1 < count);

        float4 p0, p1, q0, q1;
        if (r0 < CACHE_ROWS) {
            p0 = cache4[r0 * 64 + li];
            p1 = cache4[r0 * 64 + li + 1];
        } else {
            const float4* xr = (const float4*)(x + (gbase + r0) * (long)CDIM);
            p0 = xr[li]; p1 = xr[li + 1];
        }
        if (two) {
            if (r1 < CACHE_ROWS) {
                q0 = cache4[r1 * 64 + li];
                q1 = cache4[r1 * 64 + li + 1];
            } else {
                const float4* xr = (const float4*)(x + (gbase + r1) * (long)CDIM);
                q0 = xr[li]; q1 = xr[li + 1];
            }
        } else {
            q0 = make_float4(0.f, 0.f, 0.f, 0.f);
            q1 = make_float4(0.f, 0.f, 0.f, 0.f);
        }

        float ya[8], yb[8];
        ya[0] = p0.x + ag0.x; ya[1] = p0.y + ag0.y;
        ya[2] = p0.z + ag0.z; ya[3] = p0.w + ag0.w;
        ya[4] = p1.x + ag1.x; ya[5] = p1.y + ag1.y;
        ya[6] = p1.z + ag1.z; ya[7] = p1.w + ag1.w;
        yb[0] = q0.x + ag0.x; yb[1] = q0.y + ag0.y;
        yb[2] = q0.z + ag0.z; yb[3] = q0.w + ag0.w;
        yb[4] = q1.x + ag1.x; yb[5] = q1.y + ag1.y;
        yb[6] = q1.z + ag1.z; yb[7] = q1.w + ag1.w;

        float s0 = 0.f, ss0 = 0.f, s1 = 0.f, ss1 = 0.f;
#pragma unroll
        for (int i = 0; i < 8; ++i) {
            s0 += ya[i]; ss0 += ya[i] * ya[i];
            s1 += yb[i]; ss1 += yb[i] * yb[i];
        }
#pragma unroll
        for (int off = 16; off > 0; off >>= 1) {
            s0  += __shfl_xor_sync(0xffffffffu, s0, off);
            ss0 += __shfl_xor_sync(0xffffffffu, ss0, off);
            s1  += __shfl_xor_sync(0xffffffffu, s1, off);
            ss1 += __shfl_xor_sync(0xffffffffu, ss1, off);
        }

        const float mu0 = s0 * inv;
        const float mu1 = s1 * inv;
        const float rs0 = rsqrtf(ss0 * inv - mu0 * mu0 + LN_EPS);
        const float rs1 = rsqrtf(ss1 * inv - mu1 * mu1 + LN_EPS);

        float4 o;
        float4* or0 = (float4*)(out + (gbase + r0) * (long)CDIM);
        o.x = (ya[0] - mu0) * rs0 * g0.x + b0.x;
        o.y = (ya[1] - mu0) * rs0 * g0.y + b0.y;
        o.z = (ya[2] - mu0) * rs0 * g0.z + b0.z;
        o.w = (ya[3] - mu0) * rs0 * g0.w + b0.w;
        or0[li] = o;
        o.x = (ya[4] - mu0) * rs0 * g1.x + b1.x;
        o.y = (ya[5] - mu0) * rs0 * g1.y + b1.y;
        o.z = (ya[6] - mu0) * rs0 * g1.z + b1.z;
        o.w = (ya[7] - mu0) * rs0 * g1.w + b1.w;
        or0[li + 1] = o;
        if (two) {
            float4* or1 = (float4*)(out + (gbase + r1) * (long)CDIM);
            o.x = (yb[0] - mu1) * rs1 * g0.x + b0.x;
            o.y = (yb[1] - mu1) * rs1 * g0.y + b0.y;
            o.z = (yb[2] - mu1) * rs1 * g0.z + b0.z;
            o.w = (yb[3] - mu1) * rs1 * g0.w + b0.w;
            or1[li] = o;
            o.x = (yb[4] - mu1) * rs1 * g1.x + b1.x;
            o.y = (yb[5] - mu1) * rs1 * g1.y + b1.y;
            o.z = (yb[6] - mu1) * rs1 * g1.z + b1.z;
            o.w = (yb[7] - mu1) * rs1 * g1.w + b1.w;
            or1[li + 1] = o;
        }
    }
}

extern "C" void kernel_launch(void* const* d_in, const int* in_sizes, int n_in,
                              void* d_out, int out_size) {
    const float* x     = (const float*)d_in[0];
    const float* W     = (const float*)d_in[1];
    const float* bias  = (const float*)d_in[2];
    const float* gamma = (const float*)d_in[3];
    const float* beta  = (const float*)d_in[4];
    float* out = (float*)d_out;

    const int smem_bytes = SM_FLOATS * (int)sizeof(float);   // 56320
    cudaFuncSetAttribute(fused_gcn_ln_kernel,
                         cudaFuncAttributeMaxDynamicSharedMemorySize, smem_bytes);
    fused_gcn_ln_kernel<<<GRID, THREADS, smem_bytes>>>(x, W, bias, gamma, beta, out);
}